// round 15
// baseline (speedup 1.0000x reference)
#include <cuda_runtime.h>
#include <cstdint>
#include <math.h>

#define BB 16
#define TT 500
#define CC 2048
#define SN 64
#define SD 512
#define CLU 8                      // CTAs per den cluster
#define CPC (SD / CLU)             // 64 columns per den CTA
#define TXW (CLU * CPC * 8)        // per-phase w bytes per CTA: 8 src x 64 x 8B
#define TXM (CLU * 2 * 4)          // per-phase m bytes per CTA: 8 src x 2 x 4B

typedef unsigned long long ull;

__device__ float g_llh[2 * BB];    // [0..15] den, [16..31] num
__device__ int g_done;             // producer completion counter (self-resetting)

__device__ __forceinline__ float warp_max(float v) {
#pragma unroll
    for (int o = 16; o > 0; o >>= 1) v = fmaxf(v, __shfl_xor_sync(0xffffffffu, v, o));
    return v;
}
__device__ __forceinline__ float warp_sum(float v) {
#pragma unroll
    for (int o = 16; o > 0; o >>= 1) v += __shfl_xor_sync(0xffffffffu, v, o);
    return v;
}
__device__ __forceinline__ float clip30(float v) {
    return fminf(fmaxf(v, -30.f), 30.f);
}
__device__ __forceinline__ uint32_t smem_u32(const void* p) {
    uint32_t a;
    asm("{ .reg .u64 t; cvta.to.shared.u64 t, %1; cvt.u32.u64 %0, t; }" : "=r"(a) : "l"(p));
    return a;
}
// async remote store with transaction count on the DESTINATION CTA's mbarrier
__device__ __forceinline__ void st_async_b64(uint32_t daddr, uint32_t mbaddr, int rank, ull v) {
    uint32_t rd, rm;
    asm volatile("mapa.shared::cluster.u32 %0, %1, %2;" : "=r"(rd) : "r"(daddr), "r"(rank));
    asm volatile("mapa.shared::cluster.u32 %0, %1, %2;" : "=r"(rm) : "r"(mbaddr), "r"(rank));
    asm volatile("st.async.shared::cluster.mbarrier::complete_tx::bytes.b64 [%0], %1, [%2];"
                 :: "r"(rd), "l"(v), "r"(rm) : "memory");
}
__device__ __forceinline__ void st_async_b32(uint32_t daddr, uint32_t mbaddr, int rank, float v) {
    uint32_t rd, rm;
    asm volatile("mapa.shared::cluster.u32 %0, %1, %2;" : "=r"(rd) : "r"(daddr), "r"(rank));
    asm volatile("mapa.shared::cluster.u32 %0, %1, %2;" : "=r"(rm) : "r"(mbaddr), "r"(rank));
    asm volatile("st.async.shared::cluster.mbarrier::complete_tx::bytes.b32 [%0], %1, [%2];"
                 :: "r"(rd), "r"(__float_as_uint(v)), "r"(rm) : "memory");
}
__device__ __forceinline__ void mbar_init(uint32_t addr, uint32_t cnt) {
    asm volatile("mbarrier.init.shared.b64 [%0], %1;" :: "r"(addr), "r"(cnt) : "memory");
}
__device__ __forceinline__ void mbar_expect_tx(uint32_t addr, uint32_t bytes) {
    asm volatile("mbarrier.arrive.expect_tx.shared.b64 _, [%0], %1;"
                 :: "r"(addr), "r"(bytes) : "memory");
}
__device__ __forceinline__ void mbar_wait_parity(uint32_t mbar, uint32_t parity) {
    asm volatile(
        "{\n\t"
        ".reg .pred P1;\n\t"
        "WAIT_LOOP_%=:\n\t"
        "mbarrier.try_wait.parity.acquire.cluster.shared::cta.b64 P1, [%0], %1, 0x989680;\n\t"
        "@P1 bra.uni WAIT_DONE_%=;\n\t"
        "bra.uni WAIT_LOOP_%=;\n\t"
        "WAIT_DONE_%=:\n\t"
        "}"
        :: "r"(mbar), "r"(parity) : "memory");
}
__device__ __forceinline__ void cluster_sync_() {
    asm volatile("barrier.cluster.arrive.aligned;" ::: "memory");
    asm volatile("barrier.cluster.wait.aligned;" ::: "memory");
}
__device__ __forceinline__ uint32_t ctarank_() {
    uint32_t r;
    asm("mov.u32 %0, %%cluster_ctarank;" : "=r"(r));
    return r;
}
// packed dual-fp32 fma: d = a * b + d ; packed add
__device__ __forceinline__ void fma2(ull& d, ull a, ull b) {
    asm("fma.rn.f32x2 %0, %1, %2, %0;" : "+l"(d) : "l"(a), "l"(b));
}
__device__ __forceinline__ ull add2(ull a, ull b) {
    ull d;
    asm("add.rn.f32x2 %0, %1, %2;" : "=l"(d) : "l"(a), "l"(b));
    return d;
}

// ---------------------------------------------------------------------------
// Denominator: one 8-CTA cluster per batch, linear state, output-side norm.
// Split tx barriers (mbarW gates matvec; mbarM waited only by producers in
// slack). Matvec uses 4 independent accumulator chains (RAW depth 8 not 32);
// lagged-max combine is an explicit pairwise tree.
// ---------------------------------------------------------------------------
__device__ void den_path(const float* __restrict__ x, const int* __restrict__ seqlens,
                         const float* __restrict__ logA, const float* __restrict__ ls,
                         const float* __restrict__ lf, const int* __restrict__ ids_g) {
    __shared__ __align__(16) ull u2buf[2][SD];       // packed {w,w}, double-buffered
    __shared__ __align__(16) ull red2[16 * 32];      // [rg][cp] -> cols {2cp,2cp+1}
    __shared__ float m_arr[2][16];                   // [src CTA r][producer warp]
    __shared__ __align__(8) ull mbarW[2], mbarM[2];  // split data-ready barriers
    __shared__ float warp_red[16];

    const int tid  = threadIdx.x;
    const int lane = tid & 31, wid = tid >> 5;
    const int rg   = tid >> 5;          // matvec row group 0..15 (32 rows each)
    const int cp   = tid & 31;          // matvec column pair 0..31
    const int r    = (int)ctarank_();
    const int b    = blockIdx.x / CLU;
    const int j0   = r * CPC + 2 * cp;
    const int L    = seqlens[b];
    const float* xb = x + (size_t)b * TT * CC;

    // P slice in registers, packed per column pair
    ull pr[32];
#pragma unroll
    for (int k = 0; k < 32; ++k) {
        float2 p2;
        p2.x = __expf(logA[(size_t)(rg * 32 + k) * SD + j0]);
        p2.y = __expf(logA[(size_t)(rg * 32 + k) * SD + j0 + 1]);
        pr[k] = *(ull*)&p2;
    }

    // init + arm all barriers BEFORE any cluster traffic
    if (tid == 0) {
        mbar_init(smem_u32(&mbarW[0]), 1);
        mbar_init(smem_u32(&mbarW[1]), 1);
        mbar_init(smem_u32(&mbarM[0]), 1);
        mbar_init(smem_u32(&mbarM[1]), 1);
        mbar_expect_tx(smem_u32(&mbarW[0]), TXW);
        mbar_expect_tx(smem_u32(&mbarW[1]), TXW);
        mbar_expect_tx(smem_u32(&mbarM[0]), TXM);
        mbar_expect_tx(smem_u32(&mbarM[1]), TXM);
    }
    __syncthreads();
    cluster_sync_();    // all inits/arms visible cluster-wide before any st.async

    // t = 0 init (threads 0..63 own this CTA's 64 columns)
    int myid = 0;
    float emn = 0.f, logC = 0.f;
    const int jcol = r * CPC + tid;     // valid when tid < 64
    if (tid < 64) {
        myid = ids_g[jcol];
        float w0 = __expf(ls[jcol] + clip30(xb[myid]));
        float2 ww0 = make_float2(w0, w0);
        ull wp0 = *(ull*)&ww0;
#pragma unroll
        for (int q = 0; q < CLU; ++q)
            st_async_b64(smem_u32(&u2buf[0][jcol]), smem_u32(&mbarW[0]), q, wp0);
        float wm = warp_max(w0);
        if (lane == 0) {
#pragma unroll
            for (int q = 0; q < CLU; ++q)
                st_async_b32(smem_u32(&m_arr[0][r * 2 + wid]), smem_u32(&mbarM[0]), q, wm);
        }
        emn = (L > 1) ? xb[CC + myid] : 0.f;
    }

    int p = 0;
    unsigned uc0 = 0, uc1 = 0;          // per-buffer use counters -> phase parity
    for (int t = 1; t < L; ++t) {
        unsigned par = p ? (uc1++ & 1u) : (uc0++ & 1u);
        mbar_wait_parity(smem_u32(&mbarW[p]), par);
        // re-arm W for this buffer's NEXT fill (consumed at t+2)
        if (tid == 0) mbar_expect_tx(smem_u32(&mbarW[p]), TXW);

        // matvec partial: 32 rows x 2 cols, 4 independent accumulator chains
        ull a0 = 0ull, a1 = 0ull, a2 = 0ull, a3 = 0ull;
        const ulonglong2* uu = (const ulonglong2*)&u2buf[p][rg * 32];
#pragma unroll
        for (int k4 = 0; k4 < 4; ++k4) {
            ulonglong2 u0 = uu[4 * k4 + 0];
            ulonglong2 u1 = uu[4 * k4 + 1];
            ulonglong2 u2 = uu[4 * k4 + 2];
            ulonglong2 u3 = uu[4 * k4 + 3];
            fma2(a0, u0.x, pr[8 * k4 + 0]);
            fma2(a1, u0.y, pr[8 * k4 + 1]);
            fma2(a2, u1.x, pr[8 * k4 + 2]);
            fma2(a3, u1.y, pr[8 * k4 + 3]);
            fma2(a0, u2.x, pr[8 * k4 + 4]);
            fma2(a1, u2.y, pr[8 * k4 + 5]);
            fma2(a2, u3.x, pr[8 * k4 + 6]);
            fma2(a3, u3.y, pr[8 * k4 + 7]);
        }
        red2[rg * 32 + cp] = add2(add2(a0, a1), add2(a2, a3));
        // producer prep (64 threads): wait m (long arrived; hidden in slack)
        float E = 0.f, sc = 0.f, m = 0.f;
        if (tid < 64) {
            mbar_wait_parity(smem_u32(&mbarM[p]), par);
            if (tid == 0) mbar_expect_tx(smem_u32(&mbarM[p]), TXM);
            E = __expf(clip30(emn));
            if (t + 1 < L) emn = xb[(size_t)(t + 1) * CC + myid];
            // pairwise max tree over the 16 broadcast warp maxima
            const float* ma = m_arr[p];
            float m01 = fmaxf(ma[0], ma[1]),  m23 = fmaxf(ma[2], ma[3]);
            float m45 = fmaxf(ma[4], ma[5]),  m67 = fmaxf(ma[6], ma[7]);
            float m89 = fmaxf(ma[8], ma[9]),  mab = fmaxf(ma[10], ma[11]);
            float mcd = fmaxf(ma[12], ma[13]), mef = fmaxf(ma[14], ma[15]);
            m = fmaxf(fmaxf(fmaxf(m01, m23), fmaxf(m45, m67)),
                      fmaxf(fmaxf(m89, mab), fmaxf(mcd, mef)));
            sc = __fdividef(1.0f, m);
        }
        __syncthreads();

        if (tid < 64) {
            // reduce 16 partials for my col (4-way trees)
            const float* rf = (const float*)red2;
            float v0 = 0.f, v1 = 0.f, v2 = 0.f, v3 = 0.f;
#pragma unroll
            for (int g2 = 0; g2 < 4; ++g2) {
                v0 += rf[(4 * g2 + 0) * 64 + tid];
                v1 += rf[(4 * g2 + 1) * 64 + tid];
                v2 += rf[(4 * g2 + 2) * 64 + tid];
                v3 += rf[(4 * g2 + 3) * 64 + tid];
            }
            float w = (((v0 + v1) + (v2 + v3)) * sc) * E;   // bounded in fp32
            float2 ww = make_float2(w, w);
            ull wp2 = *(ull*)&ww;
#pragma unroll
            for (int q = 0; q < CLU; ++q)
                st_async_b64(smem_u32(&u2buf[1 - p][jcol]), smem_u32(&mbarW[1 - p]), q, wp2);
            float wm = warp_max(w);
            if (lane == 0) {
#pragma unroll
                for (int q = 0; q < CLU; ++q)
                    st_async_b32(smem_u32(&m_arr[1 - p][r * 2 + wid]), smem_u32(&mbarM[1 - p]), q, wm);
            }
            if (tid == 0) logC += __logf(m);
        }
        p ^= 1;
    }

    // final waits: prove ALL in-flight pushes landed (w by everyone, m by tid0)
    {
        unsigned par = p ? (uc1++ & 1u) : (uc0++ & 1u);
        mbar_wait_parity(smem_u32(&mbarW[p]), par);
        if (tid == 0) mbar_wait_parity(smem_u32(&mbarM[p]), par);
    }

    // llh = logC + log(sum_j w[j] * exp(lf[j]));  rank 0 has full w
    if (r == 0) {
        float w = __uint_as_float((uint32_t)u2buf[p][tid]);   // low half
        float e = w * __expf(lf[tid]);
        float ws = warp_sum(e);
        if (lane == 0) warp_red[wid] = ws;
        __syncthreads();
        if (tid == 0) {
            float s = 0.f;
            for (int i = 0; i < 16; ++i) s += warp_red[i];
            g_llh[b] = logC + __logf(s);
            __threadfence();
            atomicAdd(&g_done, 1);
        }
    }
    cluster_sync_();   // no CTA exits while peers may still receive traffic
}

// ---------------------------------------------------------------------------
// Numerator: per-batch FSM (S=64), linear state, one CTA per batch (hidden).
// ---------------------------------------------------------------------------
__device__ void num_path(int b, const float* __restrict__ x,
                         const int* __restrict__ seqlens,
                         const float* __restrict__ logA,
                         const float* __restrict__ ls,
                         const float* __restrict__ lf,
                         const int* __restrict__ ids_g) {
    __shared__ __align__(16) float Pn[SN * SN];
    __shared__ float w_n[SN];
    __shared__ float redn[8][SN];
    __shared__ float wred[2];

    const int tid = threadIdx.x;
    const int lane = tid & 31;
    const int g = tid >> 6;              // row group 0..7 (8 rows each)
    const int col = tid & 63;
    const int L = seqlens[b];
    const float* xb = x + (size_t)b * TT * CC;

    for (int i = tid; i < SN * SN; i += 512)
        Pn[i] = __expf(logA[(size_t)b * SN * SN + i]);

    int myid = 0;
    float emn = 0.f, logC = 0.f;
    if (tid < SN) {
        myid = ids_g[b * SN + tid];
        float w0 = __expf(ls[b * SN + tid] + clip30(xb[myid]));
        w_n[tid] = w0;
        float wm = warp_max(w0);
        if (lane == 0) wred[tid >> 5] = wm;
        emn = (L > 1) ? xb[CC + myid] : 0.f;
    }
    __syncthreads();

    for (int t = 1; t < L; ++t) {
        float m = fmaxf(wred[0], wred[1]);
        float E = 0.f, sc = 0.f;
        if (tid < SN) {
            sc = __fdividef(1.0f, m);
            E = __expf(clip30(emn));
            if (t + 1 < L) emn = xb[(size_t)(t + 1) * CC + myid];
        }
        float acc = 0.f;
#pragma unroll
        for (int k = 0; k < 8; ++k)
            acc = fmaf(w_n[g * 8 + k], Pn[(g * 8 + k) * SN + col], acc);
        redn[g][col] = acc;
        __syncthreads();
        if (tid < SN) {
            float v = 0.f;
#pragma unroll
            for (int g2 = 0; g2 < 8; ++g2) v += redn[g2][tid];
            float w = (v * sc) * E;
            w_n[tid] = w;
            float wm = warp_max(w);
            if (lane == 0) wred[tid >> 5] = wm;
            if (tid == 0) logC += __logf(m);
        }
        __syncthreads();
    }

    if (tid < SN) {
        float e = w_n[tid] * __expf(lf[b * SN + tid]);
        float ws = warp_sum(e);
        if (lane == 0) wred[tid >> 5] = ws;
    }
    __syncthreads();
    if (tid == 0) {
        g_llh[BB + b] = logC + __logf(wred[0] + wred[1]);
        __threadfence();
        atomicAdd(&g_done, 1);
    }
}

// Fused: clusters 0..15 (CTAs 0..127) = den; CTAs 128..143 = num batches 0..15.
// Last num CTA finalizes the output (spin on producer counter) -> ONE launch.
__global__ void __launch_bounds__(512, 1) __cluster_dims__(CLU, 1, 1)
fused_kernel(const float* __restrict__ x, const int* __restrict__ seqlens,
             const float* __restrict__ num_logA, const float* __restrict__ num_ls,
             const float* __restrict__ num_lf, const int* __restrict__ num_ids,
             const float* __restrict__ den_logA, const float* __restrict__ den_ls,
             const float* __restrict__ den_lf, const int* __restrict__ den_ids,
             float* __restrict__ out) {
    if (blockIdx.x < BB * CLU) {
        den_path(x, seqlens, den_logA, den_ls, den_lf, den_ids);
    } else {
        num_path(blockIdx.x - BB * CLU, x, seqlens, num_logA, num_ls, num_lf, num_ids);
        if (blockIdx.x == BB * CLU + BB - 1 && threadIdx.x == 0) {
            while (atomicAdd(&g_done, 0) < 2 * BB) {}
            __threadfence();
            float sden = 0.f, snum = 0.f;
            for (int i = 0; i < BB; ++i) {
                sden += g_llh[i];
                snum += g_llh[BB + i];
            }
            out[0] = -(snum - sden);
            atomicSub(&g_done, 2 * BB);   // reset for next graph replay
        }
    }
}

extern "C" void kernel_launch(void* const* d_in, const int* in_sizes, int n_in,
                              void* d_out, int out_size) {
    const float* x        = (const float*)d_in[0];
    const int*   seqlens  = (const int*)d_in[1];
    const float* num_logA = (const float*)d_in[2];
    const float* num_ls   = (const float*)d_in[3];
    const float* num_lf   = (const float*)d_in[4];
    const int*   num_ids  = (const int*)d_in[5];
    const float* den_logA = (const float*)d_in[6];
    const float* den_ls   = (const float*)d_in[7];
    const float* den_lf   = (const float*)d_in[8];
    const int*   den_ids  = (const int*)d_in[9];

    fused_kernel<<<BB * CLU + BB, 512>>>(x, seqlens, num_logA, num_ls, num_lf,
                                         num_ids, den_logA, den_ls, den_lf,
                                         den_ids, (float*)d_out);
}

// round 16
// speedup vs baseline: 1.0357x; 1.0357x over previous
#include <cuda_runtime.h>
#include <cstdint>
#include <math.h>

#define BB 16
#define TT 500
#define CC 2048
#define SN 64
#define SD 512
#define CLU 8                      // CTAs per den cluster
#define CPC (SD / CLU)             // 64 columns per den CTA
#define TXWS (CPC * 8)             // per-source w bytes per CTA: 64 x 8B = 512
#define TXM (CLU * 2 * 4)          // per-phase m bytes per CTA: 8 src x 2 x 4B

typedef unsigned long long ull;

__device__ float g_llh[2 * BB];    // [0..15] den, [16..31] num
__device__ int g_done;             // producer completion counter (self-resetting)

__device__ __forceinline__ float warp_max(float v) {
#pragma unroll
    for (int o = 16; o > 0; o >>= 1) v = fmaxf(v, __shfl_xor_sync(0xffffffffu, v, o));
    return v;
}
__device__ __forceinline__ float warp_sum(float v) {
#pragma unroll
    for (int o = 16; o > 0; o >>= 1) v += __shfl_xor_sync(0xffffffffu, v, o);
    return v;
}
__device__ __forceinline__ float clip30(float v) {
    return fminf(fmaxf(v, -30.f), 30.f);
}
__device__ __forceinline__ uint32_t smem_u32(const void* p) {
    uint32_t a;
    asm("{ .reg .u64 t; cvta.to.shared.u64 t, %1; cvt.u32.u64 %0, t; }" : "=r"(a) : "l"(p));
    return a;
}
// async remote store with transaction count on the DESTINATION CTA's mbarrier
__device__ __forceinline__ void st_async_b64(uint32_t daddr, uint32_t mbaddr, int rank, ull v) {
    uint32_t rd, rm;
    asm volatile("mapa.shared::cluster.u32 %0, %1, %2;" : "=r"(rd) : "r"(daddr), "r"(rank));
    asm volatile("mapa.shared::cluster.u32 %0, %1, %2;" : "=r"(rm) : "r"(mbaddr), "r"(rank));
    asm volatile("st.async.shared::cluster.mbarrier::complete_tx::bytes.b64 [%0], %1, [%2];"
                 :: "r"(rd), "l"(v), "r"(rm) : "memory");
}
__device__ __forceinline__ void st_async_b32(uint32_t daddr, uint32_t mbaddr, int rank, float v) {
    uint32_t rd, rm;
    asm volatile("mapa.shared::cluster.u32 %0, %1, %2;" : "=r"(rd) : "r"(daddr), "r"(rank));
    asm volatile("mapa.shared::cluster.u32 %0, %1, %2;" : "=r"(rm) : "r"(mbaddr), "r"(rank));
    asm volatile("st.async.shared::cluster.mbarrier::complete_tx::bytes.b32 [%0], %1, [%2];"
                 :: "r"(rd), "r"(__float_as_uint(v)), "r"(rm) : "memory");
}
__device__ __forceinline__ void mbar_init(uint32_t addr, uint32_t cnt) {
    asm volatile("mbarrier.init.shared.b64 [%0], %1;" :: "r"(addr), "r"(cnt) : "memory");
}
__device__ __forceinline__ void mbar_expect_tx(uint32_t addr, uint32_t bytes) {
    asm volatile("mbarrier.arrive.expect_tx.shared.b64 _, [%0], %1;"
                 :: "r"(addr), "r"(bytes) : "memory");
}
__device__ __forceinline__ void mbar_wait_parity(uint32_t mbar, uint32_t parity) {
    asm volatile(
        "{\n\t"
        ".reg .pred P1;\n\t"
        "WAIT_LOOP_%=:\n\t"
        "mbarrier.try_wait.parity.acquire.cluster.shared::cta.b64 P1, [%0], %1, 0x989680;\n\t"
        "@P1 bra.uni WAIT_DONE_%=;\n\t"
        "bra.uni WAIT_LOOP_%=;\n\t"
        "WAIT_DONE_%=:\n\t"
        "}"
        :: "r"(mbar), "r"(parity) : "memory");
}
__device__ __forceinline__ void cluster_sync_() {
    asm volatile("barrier.cluster.arrive.aligned;" ::: "memory");
    asm volatile("barrier.cluster.wait.aligned;" ::: "memory");
}
__device__ __forceinline__ uint32_t ctarank_() {
    uint32_t r;
    asm("mov.u32 %0, %%cluster_ctarank;" : "=r"(r));
    return r;
}
// packed dual-fp32 fma: d = a * b + d
__device__ __forceinline__ void fma2(ull& d, ull a, ull b) {
    asm("fma.rn.f32x2 %0, %1, %2, %0;" : "+l"(d) : "l"(a), "l"(b));
}

// ---------------------------------------------------------------------------
// Denominator: one 8-CTA cluster per batch, linear state, output-side norm.
// PER-SOURCE w barriers: warp rg's matvec reads rows [rg*32,rg*32+32) which
// come ONLY from source CTA rg>>1 -> warp waits just that source's barrier
// (512B) and starts immediately; arrival skew overlaps matvec execution.
// m barrier unchanged (waited by producers in slack).
// ---------------------------------------------------------------------------
__device__ void den_path(const float* __restrict__ x, const int* __restrict__ seqlens,
                         const float* __restrict__ logA, const float* __restrict__ ls,
                         const float* __restrict__ lf, const int* __restrict__ ids_g) {
    __shared__ __align__(16) ull u2buf[2][SD];       // packed {w,w}, double-buffered
    __shared__ __align__(16) ull red2[16 * 32];      // [rg][cp] -> cols {2cp,2cp+1}
    __shared__ float m_arr[2][16];                   // [src CTA r][producer warp]
    __shared__ __align__(8) ull mbarW8[2][CLU];      // per-source w barriers
    __shared__ __align__(8) ull mbarM[2];            // maxima barriers
    __shared__ float warp_red[16];

    const int tid  = threadIdx.x;
    const int lane = tid & 31, wid = tid >> 5;
    const int rg   = tid >> 5;          // matvec row group 0..15 (32 rows each)
    const int cp   = tid & 31;          // matvec column pair 0..31
    const int src  = rg >> 1;           // source CTA for my row group
    const int r    = (int)ctarank_();
    const int b    = blockIdx.x / CLU;
    const int j0   = r * CPC + 2 * cp;
    const int L    = seqlens[b];
    const float* xb = x + (size_t)b * TT * CC;

    // P slice in registers, packed per column pair
    ull pr[32];
#pragma unroll
    for (int k = 0; k < 32; ++k) {
        float2 p2;
        p2.x = __expf(logA[(size_t)(rg * 32 + k) * SD + j0]);
        p2.y = __expf(logA[(size_t)(rg * 32 + k) * SD + j0 + 1]);
        pr[k] = *(ull*)&p2;
    }

    // init + arm all barriers BEFORE any cluster traffic
    if (tid == 0) {
#pragma unroll
        for (int s = 0; s < CLU; ++s) {
            mbar_init(smem_u32(&mbarW8[0][s]), 1);
            mbar_init(smem_u32(&mbarW8[1][s]), 1);
            mbar_expect_tx(smem_u32(&mbarW8[0][s]), TXWS);
            mbar_expect_tx(smem_u32(&mbarW8[1][s]), TXWS);
        }
        mbar_init(smem_u32(&mbarM[0]), 1);
        mbar_init(smem_u32(&mbarM[1]), 1);
        mbar_expect_tx(smem_u32(&mbarM[0]), TXM);
        mbar_expect_tx(smem_u32(&mbarM[1]), TXM);
    }
    __syncthreads();
    cluster_sync_();    // all inits/arms visible cluster-wide before any st.async

    // t = 0 init (threads 0..63 own this CTA's 64 columns)
    int myid = 0;
    float emn = 0.f, logC = 0.f;
    const int jcol = r * CPC + tid;     // valid when tid < 64
    if (tid < 64) {
        myid = ids_g[jcol];
        float w0 = __expf(ls[jcol] + clip30(xb[myid]));
        float2 ww0 = make_float2(w0, w0);
        ull wp0 = *(ull*)&ww0;
#pragma unroll
        for (int q = 0; q < CLU; ++q)
            st_async_b64(smem_u32(&u2buf[0][jcol]), smem_u32(&mbarW8[0][r]), q, wp0);
        float wm = warp_max(w0);
        if (lane == 0) {
#pragma unroll
            for (int q = 0; q < CLU; ++q)
                st_async_b32(smem_u32(&m_arr[0][r * 2 + wid]), smem_u32(&mbarM[0]), q, wm);
        }
        emn = (L > 1) ? xb[CC + myid] : 0.f;
    }

    int p = 0;
    unsigned uc0 = 0, uc1 = 0;          // per-buffer use counters -> phase parity
    for (int t = 1; t < L; ++t) {
        unsigned par = p ? (uc1++ & 1u) : (uc0++ & 1u);
        // wait ONLY my source's slice, then start matvec immediately
        mbar_wait_parity(smem_u32(&mbarW8[p][src]), par);
        // re-arm (one thread per barrier: even warp's lane 0, after its wait)
        if ((rg & 1) == 0 && lane == 0)
            mbar_expect_tx(smem_u32(&mbarW8[p][src]), TXWS);

        // matvec partial: 32 rows x 2 cols, packed f32x2, direct on u2buf[p]
        ull acc = 0ull;
        const ulonglong2* uu = (const ulonglong2*)&u2buf[p][rg * 32];
#pragma unroll
        for (int k2 = 0; k2 < 16; ++k2) {
            ulonglong2 u = uu[k2];
            fma2(acc, u.x, pr[2 * k2]);
            fma2(acc, u.y, pr[2 * k2 + 1]);
        }
        red2[rg * 32 + cp] = acc;
        // producer prep (64 threads): wait m (long arrived; hidden in slack)
        float E = 0.f, sc = 0.f, m = 0.f;
        if (tid < 64) {
            mbar_wait_parity(smem_u32(&mbarM[p]), par);
            if (tid == 0) mbar_expect_tx(smem_u32(&mbarM[p]), TXM);
            E = __expf(clip30(emn));
            if (t + 1 < L) emn = xb[(size_t)(t + 1) * CC + myid];
            m = m_arr[p][0];
#pragma unroll
            for (int i = 1; i < 16; ++i) m = fmaxf(m, m_arr[p][i]);
            sc = __fdividef(1.0f, m);
        }
        __syncthreads();

        if (tid < 64) {
            // reduce 16 partials for my col (4-way trees)
            const float* rf = (const float*)red2;
            float v0 = 0.f, v1 = 0.f, v2 = 0.f, v3 = 0.f;
#pragma unroll
            for (int g2 = 0; g2 < 4; ++g2) {
                v0 += rf[(4 * g2 + 0) * 64 + tid];
                v1 += rf[(4 * g2 + 1) * 64 + tid];
                v2 += rf[(4 * g2 + 2) * 64 + tid];
                v3 += rf[(4 * g2 + 3) * 64 + tid];
            }
            float w = (((v0 + v1) + (v2 + v3)) * sc) * E;   // bounded in fp32
            float2 ww = make_float2(w, w);
            ull wp2 = *(ull*)&ww;
#pragma unroll
            for (int q = 0; q < CLU; ++q)
                st_async_b64(smem_u32(&u2buf[1 - p][jcol]), smem_u32(&mbarW8[1 - p][r]), q, wp2);
            float wm = warp_max(w);
            if (lane == 0) {
#pragma unroll
                for (int q = 0; q < CLU; ++q)
                    st_async_b32(smem_u32(&m_arr[1 - p][r * 2 + wid]), smem_u32(&mbarM[1 - p]), q, wm);
            }
            if (tid == 0) logC += __logf(m);
        }
        p ^= 1;
    }

    // final waits: every warp drains its own source barrier; tid0 drains m
    {
        unsigned par = p ? (uc1++ & 1u) : (uc0++ & 1u);
        mbar_wait_parity(smem_u32(&mbarW8[p][src]), par);
        if (tid == 0) mbar_wait_parity(smem_u32(&mbarM[p]), par);
    }
    __syncthreads();

    // llh = logC + log(sum_j w[j] * exp(lf[j]));  rank 0 has full w
    if (r == 0) {
        float w = __uint_as_float((uint32_t)u2buf[p][tid]);   // low half
        float e = w * __expf(lf[tid]);
        float ws = warp_sum(e);
        if (lane == 0) warp_red[wid] = ws;
        __syncthreads();
        if (tid == 0) {
            float s = 0.f;
            for (int i = 0; i < 16; ++i) s += warp_red[i];
            g_llh[b] = logC + __logf(s);
            __threadfence();
            atomicAdd(&g_done, 1);
        }
    }
    cluster_sync_();   // no CTA exits while peers may still receive traffic
}

// ---------------------------------------------------------------------------
// Numerator: per-batch FSM (S=64), linear state, one CTA per batch (hidden).
// ---------------------------------------------------------------------------
__device__ void num_path(int b, const float* __restrict__ x,
                         const int* __restrict__ seqlens,
                         const float* __restrict__ logA,
                         const float* __restrict__ ls,
                         const float* __restrict__ lf,
                         const int* __restrict__ ids_g) {
    __shared__ __align__(16) float Pn[SN * SN];
    __shared__ float w_n[SN];
    __shared__ float redn[8][SN];
    __shared__ float wred[2];

    const int tid = threadIdx.x;
    const int lane = tid & 31;
    const int g = tid >> 6;              // row group 0..7 (8 rows each)
    const int col = tid & 63;
    const int L = seqlens[b];
    const float* xb = x + (size_t)b * TT * CC;

    for (int i = tid; i < SN * SN; i += 512)
        Pn[i] = __expf(logA[(size_t)b * SN * SN + i]);

    int myid = 0;
    float emn = 0.f, logC = 0.f;
    if (tid < SN) {
        myid = ids_g[b * SN + tid];
        float w0 = __expf(ls[b * SN + tid] + clip30(xb[myid]));
        w_n[tid] = w0;
        float wm = warp_max(w0);
        if (lane == 0) wred[tid >> 5] = wm;
        emn = (L > 1) ? xb[CC + myid] : 0.f;
    }
    __syncthreads();

    for (int t = 1; t < L; ++t) {
        float m = fmaxf(wred[0], wred[1]);
        float E = 0.f, sc = 0.f;
        if (tid < SN) {
            sc = __fdividef(1.0f, m);
            E = __expf(clip30(emn));
            if (t + 1 < L) emn = xb[(size_t)(t + 1) * CC + myid];
        }
        float acc = 0.f;
#pragma unroll
        for (int k = 0; k < 8; ++k)
            acc = fmaf(w_n[g * 8 + k], Pn[(g * 8 + k) * SN + col], acc);
        redn[g][col] = acc;
        __syncthreads();
        if (tid < SN) {
            float v = 0.f;
#pragma unroll
            for (int g2 = 0; g2 < 8; ++g2) v += redn[g2][tid];
            float w = (v * sc) * E;
            w_n[tid] = w;
            float wm = warp_max(w);
            if (lane == 0) wred[tid >> 5] = wm;
            if (tid == 0) logC += __logf(m);
        }
        __syncthreads();
    }

    if (tid < SN) {
        float e = w_n[tid] * __expf(lf[b * SN + tid]);
        float ws = warp_sum(e);
        if (lane == 0) wred[tid >> 5] = ws;
    }
    __syncthreads();
    if (tid == 0) {
        g_llh[BB + b] = logC + __logf(wred[0] + wred[1]);
        __threadfence();
        atomicAdd(&g_done, 1);
    }
}

// Fused: clusters 0..15 (CTAs 0..127) = den; CTAs 128..143 = num batches 0..15.
// Last num CTA finalizes the output (spin on producer counter) -> ONE launch.
__global__ void __launch_bounds__(512, 1) __cluster_dims__(CLU, 1, 1)
fused_kernel(const float* __restrict__ x, const int* __restrict__ seqlens,
             const float* __restrict__ num_logA, const float* __restrict__ num_ls,
             const float* __restrict__ num_lf, const int* __restrict__ num_ids,
             const float* __restrict__ den_logA, const float* __restrict__ den_ls,
             const float* __restrict__ den_lf, const int* __restrict__ den_ids,
             float* __restrict__ out) {
    if (blockIdx.x < BB * CLU) {
        den_path(x, seqlens, den_logA, den_ls, den_lf, den_ids);
    } else {
        num_path(blockIdx.x - BB * CLU, x, seqlens, num_logA, num_ls, num_lf, num_ids);
        if (blockIdx.x == BB * CLU + BB - 1 && threadIdx.x == 0) {
            while (atomicAdd(&g_done, 0) < 2 * BB) {}
            __threadfence();
            float sden = 0.f, snum = 0.f;
            for (int i = 0; i < BB; ++i) {
                sden += g_llh[i];
                snum += g_llh[BB + i];
            }
            out[0] = -(snum - sden);
            atomicSub(&g_done, 2 * BB);   // reset for next graph replay
        }
    }
}

extern "C" void kernel_launch(void* const* d_in, const int* in_sizes, int n_in,
                              void* d_out, int out_size) {
    const float* x        = (const float*)d_in[0];
    const int*   seqlens  = (const int*)d_in[1];
    const float* num_logA = (const float*)d_in[2];
    const float* num_ls   = (const float*)d_in[3];
    const float* num_lf   = (const float*)d_in[4];
    const int*   num_ids  = (const int*)d_in[5];
    const float* den_logA = (const float*)d_in[6];
    const float* den_ls   = (const float*)d_in[7];
    const float* den_lf   = (const float*)d_in[8];
    const int*   den_ids  = (const int*)d_in[9];

    fused_kernel<<<BB * CLU + BB, 512>>>(x, seqlens, num_logA, num_ls, num_lf,
                                         num_ids, den_logA, den_ls, den_lf,
                                         den_ids, (float*)d_out);
}

// round 17
// speedup vs baseline: 1.0570x; 1.0206x over previous
#include <cuda_runtime.h>
#include <cstdint>
#include <math.h>

#define BB 16
#define TT 500
#define CC 2048
#define SN 64
#define SD 512
#define CLU 8                      // CTAs per den cluster
#define CPC (SD / CLU)             // 64 columns per den CTA
#define TXWS (CPC * 8)             // per-source w bytes per CTA: 64 x 8B = 512
#define TXM (CLU * 2 * 4)          // per-phase m bytes per CTA: 8 src x 2 x 4B

typedef unsigned long long ull;

__device__ float g_llh[2 * BB];    // [0..15] den, [16..31] num
__device__ int g_done;             // producer completion counter (self-resetting)

__device__ __forceinline__ float warp_max(float v) {
#pragma unroll
    for (int o = 16; o > 0; o >>= 1) v = fmaxf(v, __shfl_xor_sync(0xffffffffu, v, o));
    return v;
}
__device__ __forceinline__ float warp_sum(float v) {
#pragma unroll
    for (int o = 16; o > 0; o >>= 1) v += __shfl_xor_sync(0xffffffffu, v, o);
    return v;
}
__device__ __forceinline__ float clip30(float v) {
    return fminf(fmaxf(v, -30.f), 30.f);
}
__device__ __forceinline__ uint32_t smem_u32(const void* p) {
    uint32_t a;
    asm("{ .reg .u64 t; cvta.to.shared.u64 t, %1; cvt.u32.u64 %0, t; }" : "=r"(a) : "l"(p));
    return a;
}
// async remote store with transaction count on the DESTINATION CTA's mbarrier
__device__ __forceinline__ void st_async_b64(uint32_t daddr, uint32_t mbaddr, int rank, ull v) {
    uint32_t rd, rm;
    asm volatile("mapa.shared::cluster.u32 %0, %1, %2;" : "=r"(rd) : "r"(daddr), "r"(rank));
    asm volatile("mapa.shared::cluster.u32 %0, %1, %2;" : "=r"(rm) : "r"(mbaddr), "r"(rank));
    asm volatile("st.async.shared::cluster.mbarrier::complete_tx::bytes.b64 [%0], %1, [%2];"
                 :: "r"(rd), "l"(v), "r"(rm) : "memory");
}
__device__ __forceinline__ void st_async_b32(uint32_t daddr, uint32_t mbaddr, int rank, float v) {
    uint32_t rd, rm;
    asm volatile("mapa.shared::cluster.u32 %0, %1, %2;" : "=r"(rd) : "r"(daddr), "r"(rank));
    asm volatile("mapa.shared::cluster.u32 %0, %1, %2;" : "=r"(rm) : "r"(mbaddr), "r"(rank));
    asm volatile("st.async.shared::cluster.mbarrier::complete_tx::bytes.b32 [%0], %1, [%2];"
                 :: "r"(rd), "r"(__float_as_uint(v)), "r"(rm) : "memory");
}
__device__ __forceinline__ void mbar_init(uint32_t addr, uint32_t cnt) {
    asm volatile("mbarrier.init.shared.b64 [%0], %1;" :: "r"(addr), "r"(cnt) : "memory");
}
__device__ __forceinline__ void mbar_expect_tx(uint32_t addr, uint32_t bytes) {
    asm volatile("mbarrier.arrive.expect_tx.shared.b64 _, [%0], %1;"
                 :: "r"(addr), "r"(bytes) : "memory");
}
__device__ __forceinline__ void mbar_wait_parity(uint32_t mbar, uint32_t parity) {
    asm volatile(
        "{\n\t"
        ".reg .pred P1;\n\t"
        "WAIT_LOOP_%=:\n\t"
        "mbarrier.try_wait.parity.acquire.cluster.shared::cta.b64 P1, [%0], %1, 0x989680;\n\t"
        "@P1 bra.uni WAIT_DONE_%=;\n\t"
        "bra.uni WAIT_LOOP_%=;\n\t"
        "WAIT_DONE_%=:\n\t"
        "}"
        :: "r"(mbar), "r"(parity) : "memory");
}
__device__ __forceinline__ void cluster_sync_() {
    asm volatile("barrier.cluster.arrive.aligned;" ::: "memory");
    asm volatile("barrier.cluster.wait.aligned;" ::: "memory");
}
__device__ __forceinline__ uint32_t ctarank_() {
    uint32_t r;
    asm("mov.u32 %0, %%cluster_ctarank;" : "=r"(r));
    return r;
}
// packed dual-fp32 fma: d = a * b + d
__device__ __forceinline__ void fma2(ull& d, ull a, ull b) {
    asm("fma.rn.f32x2 %0, %1, %2, %0;" : "+l"(d) : "l"(a), "l"(b));
}

// ---------------------------------------------------------------------------
// Denominator: one 8-CTA cluster per batch, linear state, output-side norm.
// Per-source w barriers (R16) + ROTATED push schedule: producer r pushes to
// destinations q = r+1, r+2, ..., r (mod 8). Arrivals at every destination
// are staggered uniformly across issue slots instead of rank-d receiving
// everything at slot d -> the worst destination's start time improves by
// ~6 issue slots, and with per-source barriers only one warp-pair per dest
// starts late (overlapped by the others' matvec).
// ---------------------------------------------------------------------------
__device__ void den_path(const float* __restrict__ x, const int* __restrict__ seqlens,
                         const float* __restrict__ logA, const float* __restrict__ ls,
                         const float* __restrict__ lf, const int* __restrict__ ids_g) {
    __shared__ __align__(16) ull u2buf[2][SD];       // packed {w,w}, double-buffered
    __shared__ __align__(16) ull red2[16 * 32];      // [rg][cp] -> cols {2cp,2cp+1}
    __shared__ float m_arr[2][16];                   // [src CTA r][producer warp]
    __shared__ __align__(8) ull mbarW8[2][CLU];      // per-source w barriers
    __shared__ __align__(8) ull mbarM[2];            // maxima barriers
    __shared__ float warp_red[16];

    const int tid  = threadIdx.x;
    const int lane = tid & 31, wid = tid >> 5;
    const int rg   = tid >> 5;          // matvec row group 0..15 (32 rows each)
    const int cp   = tid & 31;          // matvec column pair 0..31
    const int src  = rg >> 1;           // source CTA for my row group
    const int r    = (int)ctarank_();
    const int b    = blockIdx.x / CLU;
    const int j0   = r * CPC + 2 * cp;
    const int L    = seqlens[b];
    const float* xb = x + (size_t)b * TT * CC;

    // P slice in registers, packed per column pair
    ull pr[32];
#pragma unroll
    for (int k = 0; k < 32; ++k) {
        float2 p2;
        p2.x = __expf(logA[(size_t)(rg * 32 + k) * SD + j0]);
        p2.y = __expf(logA[(size_t)(rg * 32 + k) * SD + j0 + 1]);
        pr[k] = *(ull*)&p2;
    }

    // init + arm all barriers BEFORE any cluster traffic
    if (tid == 0) {
#pragma unroll
        for (int s = 0; s < CLU; ++s) {
            mbar_init(smem_u32(&mbarW8[0][s]), 1);
            mbar_init(smem_u32(&mbarW8[1][s]), 1);
            mbar_expect_tx(smem_u32(&mbarW8[0][s]), TXWS);
            mbar_expect_tx(smem_u32(&mbarW8[1][s]), TXWS);
        }
        mbar_init(smem_u32(&mbarM[0]), 1);
        mbar_init(smem_u32(&mbarM[1]), 1);
        mbar_expect_tx(smem_u32(&mbarM[0]), TXM);
        mbar_expect_tx(smem_u32(&mbarM[1]), TXM);
    }
    __syncthreads();
    cluster_sync_();    // all inits/arms visible cluster-wide before any st.async

    // t = 0 init (threads 0..63 own this CTA's 64 columns)
    int myid = 0;
    float emn = 0.f, logC = 0.f;
    const int jcol = r * CPC + tid;     // valid when tid < 64
    if (tid < 64) {
        myid = ids_g[jcol];
        float w0 = __expf(ls[jcol] + clip30(xb[myid]));
        float2 ww0 = make_float2(w0, w0);
        ull wp0 = *(ull*)&ww0;
#pragma unroll
        for (int i = 0; i < CLU; ++i) {
            int q = (r + 1 + i) & (CLU - 1);
            st_async_b64(smem_u32(&u2buf[0][jcol]), smem_u32(&mbarW8[0][r]), q, wp0);
        }
        float wm = warp_max(w0);
        if (lane == 0) {
#pragma unroll
            for (int i = 0; i < CLU; ++i) {
                int q = (r + 1 + i) & (CLU - 1);
                st_async_b32(smem_u32(&m_arr[0][r * 2 + wid]), smem_u32(&mbarM[0]), q, wm);
            }
        }
        emn = (L > 1) ? xb[CC + myid] : 0.f;
    }

    int p = 0;
    unsigned uc0 = 0, uc1 = 0;          // per-buffer use counters -> phase parity
    for (int t = 1; t < L; ++t) {
        unsigned par = p ? (uc1++ & 1u) : (uc0++ & 1u);
        // wait ONLY my source's slice, then start matvec immediately
        mbar_wait_parity(smem_u32(&mbarW8[p][src]), par);
        // re-arm (one thread per barrier: even warp's lane 0, after its wait)
        if ((rg & 1) == 0 && lane == 0)
            mbar_expect_tx(smem_u32(&mbarW8[p][src]), TXWS);

        // matvec partial: 32 rows x 2 cols, packed f32x2, direct on u2buf[p]
        ull acc = 0ull;
        const ulonglong2* uu = (const ulonglong2*)&u2buf[p][rg * 32];
#pragma unroll
        for (int k2 = 0; k2 < 16; ++k2) {
            ulonglong2 u = uu[k2];
            fma2(acc, u.x, pr[2 * k2]);
            fma2(acc, u.y, pr[2 * k2 + 1]);
        }
        red2[rg * 32 + cp] = acc;
        // producer prep (64 threads): wait m (long arrived; hidden in slack)
        float E = 0.f, sc = 0.f, m = 0.f;
        if (tid < 64) {
            mbar_wait_parity(smem_u32(&mbarM[p]), par);
            if (tid == 0) mbar_expect_tx(smem_u32(&mbarM[p]), TXM);
            E = __expf(clip30(emn));
            if (t + 1 < L) emn = xb[(size_t)(t + 1) * CC + myid];
            m = m_arr[p][0];
#pragma unroll
            for (int i = 1; i < 16; ++i) m = fmaxf(m, m_arr[p][i]);
            sc = __fdividef(1.0f, m);
        }
        __syncthreads();

        if (tid < 64) {
            // reduce 16 partials for my col (4-way trees)
            const float* rf = (const float*)red2;
            float v0 = 0.f, v1 = 0.f, v2 = 0.f, v3 = 0.f;
#pragma unroll
            for (int g2 = 0; g2 < 4; ++g2) {
                v0 += rf[(4 * g2 + 0) * 64 + tid];
                v1 += rf[(4 * g2 + 1) * 64 + tid];
                v2 += rf[(4 * g2 + 2) * 64 + tid];
                v3 += rf[(4 * g2 + 3) * 64 + tid];
            }
            float w = (((v0 + v1) + (v2 + v3)) * sc) * E;   // bounded in fp32
            float2 ww = make_float2(w, w);
            ull wp2 = *(ull*)&ww;
#pragma unroll
            for (int i = 0; i < CLU; ++i) {
                int q = (r + 1 + i) & (CLU - 1);
                st_async_b64(smem_u32(&u2buf[1 - p][jcol]), smem_u32(&mbarW8[1 - p][r]), q, wp2);
            }
            float wm = warp_max(w);
            if (lane == 0) {
#pragma unroll
                for (int i = 0; i < CLU; ++i) {
                    int q = (r + 1 + i) & (CLU - 1);
                    st_async_b32(smem_u32(&m_arr[1 - p][r * 2 + wid]), smem_u32(&mbarM[1 - p]), q, wm);
                }
            }
            if (tid == 0) logC += __logf(m);
        }
        p ^= 1;
    }

    // final waits: every warp drains its own source barrier; tid0 drains m
    {
        unsigned par = p ? (uc1++ & 1u) : (uc0++ & 1u);
        mbar_wait_parity(smem_u32(&mbarW8[p][src]), par);
        if (tid == 0) mbar_wait_parity(smem_u32(&mbarM[p]), par);
    }
    __syncthreads();

    // llh = logC + log(sum_j w[j] * exp(lf[j]));  rank 0 has full w
    if (r == 0) {
        float w = __uint_as_float((uint32_t)u2buf[p][tid]);   // low half
        float e = w * __expf(lf[tid]);
        float ws = warp_sum(e);
        if (lane == 0) warp_red[wid] = ws;
        __syncthreads();
        if (tid == 0) {
            float s = 0.f;
            for (int i = 0; i < 16; ++i) s += warp_red[i];
            g_llh[b] = logC + __logf(s);
            __threadfence();
            atomicAdd(&g_done, 1);
        }
    }
    cluster_sync_();   // no CTA exits while peers may still receive traffic
}

// ---------------------------------------------------------------------------
// Numerator: per-batch FSM (S=64), linear state, one CTA per batch (hidden).
// ---------------------------------------------------------------------------
__device__ void num_path(int b, const float* __restrict__ x,
                         const int* __restrict__ seqlens,
                         const float* __restrict__ logA,
                         const float* __restrict__ ls,
                         const float* __restrict__ lf,
                         const int* __restrict__ ids_g) {
    __shared__ __align__(16) float Pn[SN * SN];
    __shared__ float w_n[SN];
    __shared__ float redn[8][SN];
    __shared__ float wred[2];

    const int tid = threadIdx.x;
    const int lane = tid & 31;
    const int g = tid >> 6;              // row group 0..7 (8 rows each)
    const int col = tid & 63;
    const int L = seqlens[b];
    const float* xb = x + (size_t)b * TT * CC;

    for (int i = tid; i < SN * SN; i += 512)
        Pn[i] = __expf(logA[(size_t)b * SN * SN + i]);

    int myid = 0;
    float emn = 0.f, logC = 0.f;
    if (tid < SN) {
        myid = ids_g[b * SN + tid];
        float w0 = __expf(ls[b * SN + tid] + clip30(xb[myid]));
        w_n[tid] = w0;
        float wm = warp_max(w0);
        if (lane == 0) wred[tid >> 5] = wm;
        emn = (L > 1) ? xb[CC + myid] : 0.f;
    }
    __syncthreads();

    for (int t = 1; t < L; ++t) {
        float m = fmaxf(wred[0], wred[1]);
        float E = 0.f, sc = 0.f;
        if (tid < SN) {
            sc = __fdividef(1.0f, m);
            E = __expf(clip30(emn));
            if (t + 1 < L) emn = xb[(size_t)(t + 1) * CC + myid];
        }
        float acc = 0.f;
#pragma unroll
        for (int k = 0; k < 8; ++k)
            acc = fmaf(w_n[g * 8 + k], Pn[(g * 8 + k) * SN + col], acc);
        redn[g][col] = acc;
        __syncthreads();
        if (tid < SN) {
            float v = 0.f;
#pragma unroll
            for (int g2 = 0; g2 < 8; ++g2) v += redn[g2][tid];
            float w = (v * sc) * E;
            w_n[tid] = w;
            float wm = warp_max(w);
            if (lane == 0) wred[tid >> 5] = wm;
            if (tid == 0) logC += __logf(m);
        }
        __syncthreads();
    }

    if (tid < SN) {
        float e = w_n[tid] * __expf(lf[b * SN + tid]);
        float ws = warp_sum(e);
        if (lane == 0) wred[tid >> 5] = ws;
    }
    __syncthreads();
    if (tid == 0) {
        g_llh[BB + b] = logC + __logf(wred[0] + wred[1]);
        __threadfence();
        atomicAdd(&g_done, 1);
    }
}

// Fused: clusters 0..15 (CTAs 0..127) = den; CTAs 128..143 = num batches 0..15.
// Last num CTA finalizes the output (spin on producer counter) -> ONE launch.
__global__ void __launch_bounds__(512, 1) __cluster_dims__(CLU, 1, 1)
fused_kernel(const float* __restrict__ x, const int* __restrict__ seqlens,
             const float* __restrict__ num_logA, const float* __restrict__ num_ls,
             const float* __restrict__ num_lf, const int* __restrict__ num_ids,
             const float* __restrict__ den_logA, const float* __restrict__ den_ls,
             const float* __restrict__ den_lf, const int* __restrict__ den_ids,
             float* __restrict__ out) {
    if (blockIdx.x < BB * CLU) {
        den_path(x, seqlens, den_logA, den_ls, den_lf, den_ids);
    } else {
        num_path(blockIdx.x - BB * CLU, x, seqlens, num_logA, num_ls, num_lf, num_ids);
        if (blockIdx.x == BB * CLU + BB - 1 && threadIdx.x == 0) {
            while (atomicAdd(&g_done, 0) < 2 * BB) {}
            __threadfence();
            float sden = 0.f, snum = 0.f;
            for (int i = 0; i < BB; ++i) {
                sden += g_llh[i];
                snum += g_llh[BB + i];
            }
            out[0] = -(snum - sden);
            atomicSub(&g_done, 2 * BB);   // reset for next graph replay
        }
    }
}

extern "C" void kernel_launch(void* const* d_in, const int* in_sizes, int n_in,
                              void* d_out, int out_size) {
    const float* x        = (const float*)d_in[0];
    const int*   seqlens  = (const int*)d_in[1];
    const float* num_logA = (const float*)d_in[2];
    const float* num_ls   = (const float*)d_in[3];
    const float* num_lf   = (const float*)d_in[4];
    const int*   num_ids  = (const int*)d_in[5];
    const float* den_logA = (const float*)d_in[6];
    const float* den_ls   = (const float*)d_in[7];
    const float* den_lf   = (const float*)d_in[8];
    const int*   den_ids  = (const int*)d_in[9];

    fused_kernel<<<BB * CLU + BB, 512>>>(x, seqlens, num_logA, num_ls, num_lf,
                                         num_ids, den_logA, den_ls, den_lf,
                                         den_ids, (float*)d_out);
}